// round 16
// baseline (speedup 1.0000x reference)
#include <cuda_runtime.h>
#include <cuda_fp16.h>
#include <cstdint>

#define D_MODEL 1024
#define SEQ     2048
#define BATCH   4
#define MROWS   (BATCH * SEQ)   // 8192

typedef __half h16;

// ---------------- scratch (allocation-free rule: __device__ globals) ----------------
__device__ float g_Q [MROWS * D_MODEL];
__device__ float g_K [MROWS * D_MODEL];
__device__ float g_V [MROWS * D_MODEL];
__device__ float g_S [BATCH * SEQ * SEQ];

__device__ h16 g_xb [MROWS * D_MODEL],   g_xs [MROWS * D_MODEL];
__device__ h16 g_wqb[D_MODEL * D_MODEL], g_wqs[D_MODEL * D_MODEL];
__device__ h16 g_wkb[D_MODEL * D_MODEL], g_wks[D_MODEL * D_MODEL];
__device__ h16 g_wvb[D_MODEL * D_MODEL], g_wvs[D_MODEL * D_MODEL];
__device__ h16 g_qb [MROWS * D_MODEL],   g_qs [MROWS * D_MODEL];
__device__ h16 g_kb [MROWS * D_MODEL],   g_ks [MROWS * D_MODEL];
__device__ h16 g_vb [MROWS * D_MODEL],   g_vs [MROWS * D_MODEL];     // LN(V) [s][d]
__device__ h16 g_vtb[BATCH * D_MODEL * SEQ], g_vts[BATCH * D_MODEL * SEQ]; // [d][s]
__device__ h16 g_pb [BATCH * SEQ * SEQ], g_ps [BATCH * SEQ * SEQ];

__device__ const float* g_biasptr[3];

// ---------------- helpers ----------------
__device__ __forceinline__ void h16_split_pack(float x0, float x1,
                                               uint32_t& big, uint32_t& small) {
    __half b0 = __float2half_rn(x0);
    __half b1 = __float2half_rn(x1);
    float r0 = x0 - __half2float(b0);
    float r1 = x1 - __half2float(b1);
    __half2 bb = __halves2half2(b0, b1);
    __half2 ss = __halves2half2(__float2half_rn(r0), __float2half_rn(r1));
    big   = *reinterpret_cast<uint32_t*>(&bb);
    small = *reinterpret_cast<uint32_t*>(&ss);
}

// f32-accumulate fp16 MMA (big*big)
__device__ __forceinline__ void mma_f32(float* c, const uint32_t* a, const uint32_t* b) {
    asm volatile(
        "mma.sync.aligned.m16n8k16.row.col.f32.f16.f16.f32 "
        "{%0,%1,%2,%3}, {%4,%5,%6,%7}, {%8,%9}, {%0,%1,%2,%3};\n"
        : "+f"(c[0]), "+f"(c[1]), "+f"(c[2]), "+f"(c[3])
        : "r"(a[0]), "r"(a[1]), "r"(a[2]), "r"(a[3]), "r"(b[0]), "r"(b[1]));
}
// f16-accumulate fp16 MMA (cross terms)
__device__ __forceinline__ void mma_f16(uint32_t* c, const uint32_t* a, const uint32_t* b) {
    asm volatile(
        "mma.sync.aligned.m16n8k16.row.col.f16.f16.f16.f16 "
        "{%0,%1}, {%2,%3,%4,%5}, {%6,%7}, {%0,%1};\n"
        : "+r"(c[0]), "+r"(c[1])
        : "r"(a[0]), "r"(a[1]), "r"(a[2]), "r"(a[3]), "r"(b[0]), "r"(b[1]));
}

__device__ __forceinline__ float block_reduce_sum(float v, float* red) {
#pragma unroll
    for (int o = 16; o > 0; o >>= 1) v += __shfl_xor_sync(0xffffffffu, v, o);
    if ((threadIdx.x & 31) == 0) red[threadIdx.x >> 5] = v;
    __syncthreads();
    float tot = 0.f;
#pragma unroll
    for (int i = 0; i < 8; i++) tot += red[i];
    __syncthreads();
    return tot;
}
__device__ __forceinline__ float block_reduce_max(float v, float* red) {
#pragma unroll
    for (int o = 16; o > 0; o >>= 1) v = fmaxf(v, __shfl_xor_sync(0xffffffffu, v, o));
    if ((threadIdx.x & 31) == 0) red[threadIdx.x >> 5] = v;
    __syncthreads();
    float tot = -3.4e38f;
#pragma unroll
    for (int i = 0; i < 8; i++) tot = fmaxf(tot, red[i]);
    __syncthreads();
    return tot;
}

// ---------------- 3xFP16 GEMM core: f32-acc big*big + f16-acc cross ----------------
// C[m,n] = sum_k A[m,k]*B[n,k] (+bias[n]); pre-split fp16 big/small row-major.
// Block tile 128x64, K-chunk 32, 256 threads (8 warps of 32x32), 2 CTAs/SM.
// Smem: A buffers [128][20] words, B buffers [64][20]; stride 20 -> conflict-free LDS.
// Per k16 tile: 1x mma_f32 (bb) + 2x mma_f16 (bs, sb). Cross drained in epilogue.
__device__ __forceinline__ void gemm_h3(
    const h16* __restrict__ Ab, const h16* __restrict__ As, int lda,
    const h16* __restrict__ Bb, const h16* __restrict__ Bs, int ldb,
    float* __restrict__ C, int ldc,
    int K, const float* __restrict__ bias)
{
    __shared__ uint32_t sAb[128][20], sAs[128][20];
    __shared__ uint32_t sBb[64][20],  sBs[64][20];

    const int tid  = threadIdx.x;
    const int warp = tid >> 5, lane = tid & 31;
    const int g = lane >> 2, tg = lane & 3;
    const int wm0 = (warp >> 1) * 32;   // 0,32,64,96
    const int wn0 = (warp & 1) * 32;    // 0 or 32

    const int row0 = blockIdx.x * 128;
    const int n0   = blockIdx.y * 64;

    const h16* Ab0 = Ab + (size_t)row0 * lda;
    const h16* As0 = As + (size_t)row0 * lda;
    const h16* Bb0 = Bb + (size_t)n0   * ldb;
    const h16* Bs0 = Bs + (size_t)n0   * ldb;

    float    acc[2][4][4];
    uint32_t c16[2][4][2];
#pragma unroll
    for (int i = 0; i < 2; i++)
#pragma unroll
        for (int j = 0; j < 4; j++) {
#pragma unroll
            for (int r = 0; r < 4; r++) acc[i][j][r] = 0.f;
            c16[i][j][0] = 0u; c16[i][j][1] = 0u;
        }

    // fill mappings
    const int br = tid >> 2;            // B: 1 load/thread, r = 0..63
    const int bc = (tid & 3) << 2;

    for (int k0 = 0; k0 < K; k0 += 32) {
        // A: 512 16B-loads (2/thread), coalesced 4-threads-per-row
#pragma unroll
        for (int i = 0; i < 2; i++) {
            int idx = tid + 256 * i;
            int r   = idx >> 2;
            int cw  = (idx & 3) << 2;
            int ke  = k0 + (cw << 1);
            *reinterpret_cast<uint4*>(&sAb[r][cw]) =
                *reinterpret_cast<const uint4*>(Ab0 + (size_t)r * lda + ke);
            *reinterpret_cast<uint4*>(&sAs[r][cw]) =
                *reinterpret_cast<const uint4*>(As0 + (size_t)r * lda + ke);
        }
        // B: 256 16B-loads (1/thread)
        {
            int ke = k0 + (bc << 1);
            *reinterpret_cast<uint4*>(&sBb[br][bc]) =
                *reinterpret_cast<const uint4*>(Bb0 + (size_t)br * ldb + ke);
            *reinterpret_cast<uint4*>(&sBs[br][bc]) =
                *reinterpret_cast<const uint4*>(Bs0 + (size_t)br * ldb + ke);
        }
        __syncthreads();

#pragma unroll
        for (int s = 0; s < 2; s++) {
            const int kb = s * 8;
            uint32_t bfb[4][2], bfs[4][2];
#pragma unroll
            for (int j = 0; j < 4; j++) {
                int n = wn0 + 8 * j;
                bfb[j][0] = sBb[n + g][kb + tg];
                bfb[j][1] = sBb[n + g][kb + 4 + tg];
                bfs[j][0] = sBs[n + g][kb + tg];
                bfs[j][1] = sBs[n + g][kb + 4 + tg];
            }
#pragma unroll
            for (int i = 0; i < 2; i++) {
                int m = wm0 + 16 * i;
                uint32_t afb[4], afs[4];
                afb[0] = sAb[m + g    ][kb + tg];
                afb[1] = sAb[m + g + 8][kb + tg];
                afb[2] = sAb[m + g    ][kb + 4 + tg];
                afb[3] = sAb[m + g + 8][kb + 4 + tg];
                afs[0] = sAs[m + g    ][kb + tg];
                afs[1] = sAs[m + g + 8][kb + tg];
                afs[2] = sAs[m + g    ][kb + 4 + tg];
                afs[3] = sAs[m + g + 8][kb + 4 + tg];
#pragma unroll
                for (int j = 0; j < 4; j++) mma_f32(acc[i][j], afb, bfb[j]);  // big*big
#pragma unroll
                for (int j = 0; j < 4; j++) mma_f16(c16[i][j], afb, bfs[j]);  // big*small
#pragma unroll
                for (int j = 0; j < 4; j++) mma_f16(c16[i][j], afs, bfb[j]);  // small*big
            }
        }
        __syncthreads();
    }

    // epilogue: acc + cross(f16) + bias
#pragma unroll
    for (int i = 0; i < 2; i++) {
        int m = row0 + wm0 + 16 * i;
#pragma unroll
        for (int j = 0; j < 4; j++) {
            int n = n0 + wn0 + 8 * j + 2 * tg;
            float b0 = 0.f, b1 = 0.f;
            if (bias) { b0 = bias[n]; b1 = bias[n + 1]; }
            float2 x0 = __half22float2(*reinterpret_cast<__half2*>(&c16[i][j][0]));
            float2 x1 = __half22float2(*reinterpret_cast<__half2*>(&c16[i][j][1]));
            float2 v0 = make_float2(acc[i][j][0] + x0.x + b0, acc[i][j][1] + x0.y + b1);
            float2 v1 = make_float2(acc[i][j][2] + x1.x + b0, acc[i][j][3] + x1.y + b1);
            *reinterpret_cast<float2*>(C + (size_t)(m + g    ) * ldc + n) = v0;
            *reinterpret_cast<float2*>(C + (size_t)(m + g + 8) * ldc + n) = v1;
        }
    }
}

// ---------------- kernels ----------------
__global__ void __launch_bounds__(256) split_all_kernel(
    const float* __restrict__ x,  const float* __restrict__ Wq,
    const float* __restrict__ Wk, const float* __restrict__ Wv)
{
    const float* in; h16* big; h16* small; int n4;
    switch (blockIdx.y) {
        case 0:  in = x;  big = g_xb;  small = g_xs;  n4 = MROWS * D_MODEL / 4; break;
        case 1:  in = Wq; big = g_wqb; small = g_wqs; n4 = D_MODEL * D_MODEL / 4; break;
        case 2:  in = Wk; big = g_wkb; small = g_wks; n4 = D_MODEL * D_MODEL / 4; break;
        default: in = Wv; big = g_wvb; small = g_wvs; n4 = D_MODEL * D_MODEL / 4; break;
    }
    int i = blockIdx.x * blockDim.x + threadIdx.x;
    if (i < n4) {
        float4 v = reinterpret_cast<const float4*>(in)[i];
        uint32_t b01, s01, b23, s23;
        h16_split_pack(v.x, v.y, b01, s01);
        h16_split_pack(v.z, v.w, b23, s23);
        reinterpret_cast<uint2*>(big)[i]   = make_uint2(b01, b23);
        reinterpret_cast<uint2*>(small)[i] = make_uint2(s01, s23);
    }
}

__global__ void __launch_bounds__(32) set_bias_kernel(const float* bq, const float* bk, const float* bv)
{
    if (threadIdx.x == 0) { g_biasptr[0] = bq; g_biasptr[1] = bk; g_biasptr[2] = bv; }
}

__global__ void __launch_bounds__(256, 2) proj_kernel()
{
    const h16* Wb; const h16* Ws; float* Cout;
    if (blockIdx.z == 0)      { Wb = g_wqb; Ws = g_wqs; Cout = g_Q; }
    else if (blockIdx.z == 1) { Wb = g_wkb; Ws = g_wks; Cout = g_K; }
    else                      { Wb = g_wvb; Ws = g_wvs; Cout = g_V; }
    gemm_h3(g_xb, g_xs, D_MODEL, Wb, Ws, D_MODEL, Cout, D_MODEL, D_MODEL,
            g_biasptr[blockIdx.z]);
}

// LayerNorm; all outputs written coalesced [row][d] as split fp16.
__global__ void __launch_bounds__(256) ln_kernel(
    const float* __restrict__ gamma, const float* __restrict__ beta)
{
    __shared__ float red[8];
    const int row   = blockIdx.x;
    const int which = blockIdx.y;
    const float* src = ((which == 0) ? g_Q : (which == 1) ? g_K : g_V) + (size_t)row * D_MODEL;
    const int t = threadIdx.x;

    float4 v = reinterpret_cast<const float4*>(src)[t];
    float s = v.x + v.y + v.z + v.w;
    s = block_reduce_sum(s, red);
    const float mean = s * (1.0f / D_MODEL);
    const float dx = v.x - mean, dy = v.y - mean, dz = v.z - mean, dw = v.w - mean;
    float sq = dx * dx + dy * dy + dz * dz + dw * dw;
    sq = block_reduce_sum(sq, red);
    const float rstd = rsqrtf(sq * (1.0f / D_MODEL) + 1e-5f);

    const float4 ga = reinterpret_cast<const float4*>(gamma)[t];
    const float4 be = reinterpret_cast<const float4*>(beta)[t];
    float ox = dx * rstd * ga.x + be.x;
    float oy = dy * rstd * ga.y + be.y;
    float oz = dz * rstd * ga.z + be.z;
    float ow = dw * rstd * ga.w + be.w;

    uint32_t b01, s01, b23, s23;
    h16_split_pack(ox, oy, b01, s01);
    h16_split_pack(oz, ow, b23, s23);

    h16* big   = (which == 0) ? g_qb : (which == 1) ? g_kb : g_vb;
    h16* small = (which == 0) ? g_qs : (which == 1) ? g_ks : g_vs;
    size_t o = (size_t)row * D_MODEL;
    reinterpret_cast<uint2*>(big + o)[t]   = make_uint2(b01, b23);
    reinterpret_cast<uint2*>(small + o)[t] = make_uint2(s01, s23);
}

// transpose LN(V): [b][s][d] -> [b][d][s], 64x64 tiles, conflict-free smem
__global__ void __launch_bounds__(256) vt_kernel()
{
    __shared__ h16 tb[64][66], ts[64][66];
    const int s0 = blockIdx.x * 64;
    const int d0 = blockIdx.y * 64;
    const int b  = blockIdx.z;
    const int t  = threadIdx.x;
    const h16* vb = g_vb + (size_t)b * SEQ * D_MODEL;
    const h16* vs = g_vs + (size_t)b * SEQ * D_MODEL;
#pragma unroll
    for (int q = 0; q < 16; q++) {
        int idx = t + 256 * q;
        int sl = idx >> 6, dl = idx & 63;
        tb[sl][dl] = vb[(size_t)(s0 + sl) * D_MODEL + d0 + dl];
        ts[sl][dl] = vs[(size_t)(s0 + sl) * D_MODEL + d0 + dl];
    }
    __syncthreads();
    h16* ob = g_vtb + (size_t)b * D_MODEL * SEQ;
    h16* os = g_vts + (size_t)b * D_MODEL * SEQ;
#pragma unroll
    for (int q = 0; q < 16; q++) {
        int idx = t + 256 * q;
        int dl = idx >> 6, sl = idx & 63;
        ob[(size_t)(d0 + dl) * SEQ + s0 + sl] = tb[sl][dl];
        os[(size_t)(d0 + dl) * SEQ + s0 + sl] = ts[sl][dl];
    }
}

__global__ void __launch_bounds__(256, 2) qk_kernel()
{
    const size_t bz = blockIdx.z;
    gemm_h3(g_qb + bz * SEQ * D_MODEL, g_qs + bz * SEQ * D_MODEL, D_MODEL,
            g_kb + bz * SEQ * D_MODEL, g_ks + bz * SEQ * D_MODEL, D_MODEL,
            g_S + bz * SEQ * SEQ, SEQ,
            D_MODEL, nullptr);
}

__global__ void __launch_bounds__(256) softmax_kernel()
{
    __shared__ float red[8];
    const size_t row = (size_t)blockIdx.y * SEQ + blockIdx.x;
    const float* p = g_S + row * SEQ;
    const int t = threadIdx.x;

    float4 u0 = reinterpret_cast<const float4*>(p)[t];
    float4 u1 = reinterpret_cast<const float4*>(p)[t + 256];
    float m = fmaxf(fmaxf(fmaxf(u0.x, u0.y), fmaxf(u0.z, u0.w)),
                    fmaxf(fmaxf(u1.x, u1.y), fmaxf(u1.z, u1.w)));
    m = block_reduce_max(m, red);

    u0.x = expf(u0.x - m); u0.y = expf(u0.y - m); u0.z = expf(u0.z - m); u0.w = expf(u0.w - m);
    u1.x = expf(u1.x - m); u1.y = expf(u1.y - m); u1.z = expf(u1.z - m); u1.w = expf(u1.w - m);
    float s = (u0.x + u0.y + u0.z + u0.w) + (u1.x + u1.y + u1.z + u1.w);
    s = block_reduce_sum(s, red);
    const float inv = 1.0f / s;

    u0.x *= inv; u0.y *= inv; u0.z *= inv; u0.w *= inv;
    u1.x *= inv; u1.y *= inv; u1.z *= inv; u1.w *= inv;

    uint32_t b01, s01, b23, s23;
    h16* pb = g_pb + row * SEQ;
    h16* ps = g_ps + row * SEQ;
    h16_split_pack(u0.x, u0.y, b01, s01);
    h16_split_pack(u0.z, u0.w, b23, s23);
    reinterpret_cast<uint2*>(pb)[t]       = make_uint2(b01, b23);
    reinterpret_cast<uint2*>(ps)[t]       = make_uint2(s01, s23);
    h16_split_pack(u1.x, u1.y, b01, s01);
    h16_split_pack(u1.z, u1.w, b23, s23);
    reinterpret_cast<uint2*>(pb)[t + 256] = make_uint2(b01, b23);
    reinterpret_cast<uint2*>(ps)[t + 256] = make_uint2(s01, s23);
}

__global__ void __launch_bounds__(256, 2) pv_kernel(float* __restrict__ out)
{
    const size_t bz = blockIdx.z;
    gemm_h3(g_pb  + bz * SEQ * SEQ, g_ps  + bz * SEQ * SEQ, SEQ,
            g_vtb + bz * D_MODEL * SEQ, g_vts + bz * D_MODEL * SEQ, SEQ,
            out   + bz * SEQ * D_MODEL, D_MODEL,
            SEQ, nullptr);
}

// ---------------- launch ----------------
extern "C" void kernel_launch(void* const* d_in, const int* in_sizes, int n_in,
                              void* d_out, int out_size)
{
    const float* x     = (const float*)d_in[0];
    const float* Wq    = (const float*)d_in[1];
    const float* bq    = (const float*)d_in[2];
    const float* Wk    = (const float*)d_in[3];
    const float* bk    = (const float*)d_in[4];
    const float* Wv    = (const float*)d_in[5];
    const float* bv    = (const float*)d_in[6];
    const float* gamma = (const float*)d_in[7];
    const float* beta  = (const float*)d_in[8];
    float* out = (float*)d_out;

    dim3 tpb(256);
    set_bias_kernel<<<1, 32>>>(bq, bk, bv);
    split_all_kernel<<<dim3(MROWS * D_MODEL / 4 / 256, 4), tpb>>>(x, Wq, Wk, Wv);

    proj_kernel   <<<dim3(MROWS / 128, D_MODEL / 64, 3), tpb>>>();
    ln_kernel     <<<dim3(MROWS, 3), tpb>>>(gamma, beta);
    vt_kernel     <<<dim3(SEQ / 64, D_MODEL / 64, BATCH), tpb>>>();
    qk_kernel     <<<dim3(SEQ / 128, SEQ / 64, BATCH), tpb>>>();
    softmax_kernel<<<dim3(SEQ, BATCH), tpb>>>();
    pv_kernel     <<<dim3(SEQ / 128, D_MODEL / 64, BATCH), tpb>>>(out);
}

// round 17
// speedup vs baseline: 2.0148x; 2.0148x over previous
#include <cuda_runtime.h>
#include <cuda_fp16.h>
#include <cstdint>

#define D_MODEL 1024
#define SEQ     2048
#define BATCH   4
#define MROWS   (BATCH * SEQ)   // 8192

typedef __half h16;

// ---------------- scratch (allocation-free rule: __device__ globals) ----------------
__device__ float g_Q [MROWS * D_MODEL];
__device__ float g_K [MROWS * D_MODEL];
__device__ float g_V [MROWS * D_MODEL];
__device__ float g_S [BATCH * SEQ * SEQ];

__device__ h16 g_xb [MROWS * D_MODEL],   g_xs [MROWS * D_MODEL];
__device__ h16 g_wqb[D_MODEL * D_MODEL], g_wqs[D_MODEL * D_MODEL];
__device__ h16 g_wkb[D_MODEL * D_MODEL], g_wks[D_MODEL * D_MODEL];
__device__ h16 g_wvb[D_MODEL * D_MODEL], g_wvs[D_MODEL * D_MODEL];
__device__ h16 g_qb [MROWS * D_MODEL],   g_qs [MROWS * D_MODEL];
__device__ h16 g_kb [MROWS * D_MODEL],   g_ks [MROWS * D_MODEL];
__device__ h16 g_vb [MROWS * D_MODEL],   g_vs [MROWS * D_MODEL];     // LN(V) [s][d]
__device__ h16 g_vtb[BATCH * D_MODEL * SEQ], g_vts[BATCH * D_MODEL * SEQ]; // [d][s]
__device__ h16 g_pb [BATCH * SEQ * SEQ], g_ps [BATCH * SEQ * SEQ];

__device__ const float* g_biasptr[3];

// ---------------- helpers ----------------
__device__ __forceinline__ void h16_split_pack(float x0, float x1,
                                               uint32_t& big, uint32_t& small) {
    __half b0 = __float2half_rn(x0);
    __half b1 = __float2half_rn(x1);
    float r0 = x0 - __half2float(b0);
    float r1 = x1 - __half2float(b1);
    __half2 bb = __halves2half2(b0, b1);
    __half2 ss = __halves2half2(__float2half_rn(r0), __float2half_rn(r1));
    big   = *reinterpret_cast<uint32_t*>(&bb);
    small = *reinterpret_cast<uint32_t*>(&ss);
}

__device__ __forceinline__ void mma16(float* c, const uint32_t* a, const uint32_t* b) {
    asm volatile(
        "mma.sync.aligned.m16n8k16.row.col.f32.f16.f16.f32 "
        "{%0,%1,%2,%3}, {%4,%5,%6,%7}, {%8,%9}, {%0,%1,%2,%3};\n"
        : "+f"(c[0]), "+f"(c[1]), "+f"(c[2]), "+f"(c[3])
        : "r"(a[0]), "r"(a[1]), "r"(a[2]), "r"(a[3]), "r"(b[0]), "r"(b[1]));
}

__device__ __forceinline__ float block_reduce_sum(float v, float* red) {
#pragma unroll
    for (int o = 16; o > 0; o >>= 1) v += __shfl_xor_sync(0xffffffffu, v, o);
    if ((threadIdx.x & 31) == 0) red[threadIdx.x >> 5] = v;
    __syncthreads();
    float tot = 0.f;
#pragma unroll
    for (int i = 0; i < 8; i++) tot += red[i];
    __syncthreads();
    return tot;
}
__device__ __forceinline__ float block_reduce_max(float v, float* red) {
#pragma unroll
    for (int o = 16; o > 0; o >>= 1) v = fmaxf(v, __shfl_xor_sync(0xffffffffu, v, o));
    if ((threadIdx.x & 31) == 0) red[threadIdx.x >> 5] = v;
    __syncthreads();
    float tot = -3.4e38f;
#pragma unroll
    for (int i = 0; i < 8; i++) tot = fmaxf(tot, red[i]);
    __syncthreads();
    return tot;
}

// ---------------- FP16-split GEMM core (f32 accumulate), pre-split operands --------
// C[m,n] = sum_k A[m,k]*B[n,k] (+bias[n]); A,B given as big/small fp16 row-major.
// Block tile 128x128, K-chunk 32, 256 threads (8 warps of 64x32 warp tiles), 2 CTAs/SM.
// Smem: 4 buffers [128 rows][20 words]; stride 20 -> conflict-free fragment LDS.
// Fill: 4 threads per row -> 64B contiguous global runs (full sectors).
// NTERMS=3: Ab*Bs + As*Bb + Ab*Bb.  NTERMS=2: As*Bb + Ab*Bb (drops B-residual term;
// used for P·V where the dropped term is ~2.4e-4 relative — see round notes).
template <int NTERMS>
__device__ __forceinline__ void gemm_h3(
    const h16* __restrict__ Ab, const h16* __restrict__ As, int lda,
    const h16* __restrict__ Bb, const h16* __restrict__ Bs, int ldb,
    float* __restrict__ C, int ldc,
    int K, const float* __restrict__ bias)
{
    __shared__ uint32_t sAb[128][20], sAs[128][20];
    __shared__ uint32_t sBb[128][20], sBs[128][20];

    const int tid  = threadIdx.x;
    const int warp = tid >> 5, lane = tid & 31;
    const int g = lane >> 2, tg = lane & 3;
    const int wm0 = (warp >> 2) * 64;   // 0 or 64
    const int wn0 = (warp & 3) * 32;    // 0..96

    const int row0 = blockIdx.x * 128;
    const int n0   = blockIdx.y * 128;

    const h16* Ab0 = Ab + (size_t)row0 * lda;
    const h16* As0 = As + (size_t)row0 * lda;
    const h16* Bb0 = Bb + (size_t)n0   * ldb;
    const h16* Bs0 = Bs + (size_t)n0   * ldb;

    float acc[4][4][4];
#pragma unroll
    for (int i = 0; i < 4; i++)
#pragma unroll
        for (int j = 0; j < 4; j++)
#pragma unroll
            for (int r = 0; r < 4; r++) acc[i][j][r] = 0.f;

    for (int k0 = 0; k0 < K; k0 += 32) {
        // coalesced fill: 4 threads per row, each uint4 = 8 halves (16B), 64B/row runs
#pragma unroll
        for (int i = 0; i < 2; i++) {
            int idx = tid + 256 * i;            // 0..511
            int r   = idx >> 2;                 // 0..127
            int cw  = (idx & 3) << 2;           // word col: 0,4,8,12
            int ke  = k0 + (cw << 1);           // element offset
            *reinterpret_cast<uint4*>(&sAb[r][cw]) =
                *reinterpret_cast<const uint4*>(Ab0 + (size_t)r * lda + ke);
            *reinterpret_cast<uint4*>(&sAs[r][cw]) =
                *reinterpret_cast<const uint4*>(As0 + (size_t)r * lda + ke);
            *reinterpret_cast<uint4*>(&sBb[r][cw]) =
                *reinterpret_cast<const uint4*>(Bb0 + (size_t)r * ldb + ke);
            if (NTERMS == 3)
                *reinterpret_cast<uint4*>(&sBs[r][cw]) =
                    *reinterpret_cast<const uint4*>(Bs0 + (size_t)r * ldb + ke);
        }
        __syncthreads();

#pragma unroll
        for (int s = 0; s < 2; s++) {           // two k16 steps per k32 chunk
            const int kb = s * 8;               // word base
            uint32_t bfb[4][2], bfs[4][2];
#pragma unroll
            for (int j = 0; j < 4; j++) {
                int n = wn0 + 8 * j;
                bfb[j][0] = sBb[n + g][kb + tg];
                bfb[j][1] = sBb[n + g][kb + 4 + tg];
                if (NTERMS == 3) {
                    bfs[j][0] = sBs[n + g][kb + tg];
                    bfs[j][1] = sBs[n + g][kb + 4 + tg];
                }
            }
#pragma unroll
            for (int i = 0; i < 4; i++) {
                int m = wm0 + 16 * i;
                uint32_t afb[4], afs[4];
                afb[0] = sAb[m + g    ][kb + tg];
                afb[1] = sAb[m + g + 8][kb + tg];
                afb[2] = sAb[m + g    ][kb + 4 + tg];
                afb[3] = sAb[m + g + 8][kb + 4 + tg];
                afs[0] = sAs[m + g    ][kb + tg];
                afs[1] = sAs[m + g + 8][kb + tg];
                afs[2] = sAs[m + g    ][kb + 4 + tg];
                afs[3] = sAs[m + g + 8][kb + 4 + tg];
                if (NTERMS == 3) {
#pragma unroll
                    for (int j = 0; j < 4; j++) mma16(acc[i][j], afb, bfs[j]);  // big*small
                }
#pragma unroll
                for (int j = 0; j < 4; j++) mma16(acc[i][j], afs, bfb[j]);      // small*big
#pragma unroll
                for (int j = 0; j < 4; j++) mma16(acc[i][j], afb, bfb[j]);      // big*big
            }
        }
        __syncthreads();
    }

    // epilogue
#pragma unroll
    for (int i = 0; i < 4; i++) {
        int m = row0 + wm0 + 16 * i;
#pragma unroll
        for (int j = 0; j < 4; j++) {
            int n = n0 + wn0 + 8 * j + 2 * tg;
            float b0 = 0.f, b1 = 0.f;
            if (bias) { b0 = bias[n]; b1 = bias[n + 1]; }
            float2 v0 = make_float2(acc[i][j][0] + b0, acc[i][j][1] + b1);
            float2 v1 = make_float2(acc[i][j][2] + b0, acc[i][j][3] + b1);
            *reinterpret_cast<float2*>(C + (size_t)(m + g    ) * ldc + n) = v0;
            *reinterpret_cast<float2*>(C + (size_t)(m + g + 8) * ldc + n) = v1;
        }
    }
}

// ---------------- kernels ----------------
__global__ void __launch_bounds__(256) split_all_kernel(
    const float* __restrict__ x,  const float* __restrict__ Wq,
    const float* __restrict__ Wk, const float* __restrict__ Wv)
{
    const float* in; h16* big; h16* small; int n4;
    switch (blockIdx.y) {
        case 0:  in = x;  big = g_xb;  small = g_xs;  n4 = MROWS * D_MODEL / 4; break;
        case 1:  in = Wq; big = g_wqb; small = g_wqs; n4 = D_MODEL * D_MODEL / 4; break;
        case 2:  in = Wk; big = g_wkb; small = g_wks; n4 = D_MODEL * D_MODEL / 4; break;
        default: in = Wv; big = g_wvb; small = g_wvs; n4 = D_MODEL * D_MODEL / 4; break;
    }
    int i = blockIdx.x * blockDim.x + threadIdx.x;
    if (i < n4) {
        float4 v = reinterpret_cast<const float4*>(in)[i];
        uint32_t b01, s01, b23, s23;
        h16_split_pack(v.x, v.y, b01, s01);
        h16_split_pack(v.z, v.w, b23, s23);
        reinterpret_cast<uint2*>(big)[i]   = make_uint2(b01, b23);
        reinterpret_cast<uint2*>(small)[i] = make_uint2(s01, s23);
    }
}

__global__ void __launch_bounds__(32) set_bias_kernel(const float* bq, const float* bk, const float* bv)
{
    if (threadIdx.x == 0) { g_biasptr[0] = bq; g_biasptr[1] = bk; g_biasptr[2] = bv; }
}

__global__ void __launch_bounds__(256, 2) proj_kernel()
{
    const h16* Wb; const h16* Ws; float* Cout;
    if (blockIdx.z == 0)      { Wb = g_wqb; Ws = g_wqs; Cout = g_Q; }
    else if (blockIdx.z == 1) { Wb = g_wkb; Ws = g_wks; Cout = g_K; }
    else                      { Wb = g_wvb; Ws = g_wvs; Cout = g_V; }
    gemm_h3<3>(g_xb, g_xs, D_MODEL, Wb, Ws, D_MODEL, Cout, D_MODEL, D_MODEL,
               g_biasptr[blockIdx.z]);
}

// LayerNorm; all outputs written coalesced [row][d] as split fp16.
__global__ void __launch_bounds__(256) ln_kernel(
    const float* __restrict__ gamma, const float* __restrict__ beta)
{
    __shared__ float red[8];
    const int row   = blockIdx.x;
    const int which = blockIdx.y;
    const float* src = ((which == 0) ? g_Q : (which == 1) ? g_K : g_V) + (size_t)row * D_MODEL;
    const int t = threadIdx.x;

    float4 v = reinterpret_cast<const float4*>(src)[t];
    float s = v.x + v.y + v.z + v.w;
    s = block_reduce_sum(s, red);
    const float mean = s * (1.0f / D_MODEL);
    const float dx = v.x - mean, dy = v.y - mean, dz = v.z - mean, dw = v.w - mean;
    float sq = dx * dx + dy * dy + dz * dz + dw * dw;
    sq = block_reduce_sum(sq, red);
    const float rstd = rsqrtf(sq * (1.0f / D_MODEL) + 1e-5f);

    const float4 ga = reinterpret_cast<const float4*>(gamma)[t];
    const float4 be = reinterpret_cast<const float4*>(beta)[t];
    float ox = dx * rstd * ga.x + be.x;
    float oy = dy * rstd * ga.y + be.y;
    float oz = dz * rstd * ga.z + be.z;
    float ow = dw * rstd * ga.w + be.w;

    uint32_t b01, s01, b23, s23;
    h16_split_pack(ox, oy, b01, s01);
    h16_split_pack(oz, ow, b23, s23);

    h16* big   = (which == 0) ? g_qb : (which == 1) ? g_kb : g_vb;
    h16* small = (which == 0) ? g_qs : (which == 1) ? g_ks : g_vs;
    size_t o = (size_t)row * D_MODEL;
    reinterpret_cast<uint2*>(big + o)[t]   = make_uint2(b01, b23);
    reinterpret_cast<uint2*>(small + o)[t] = make_uint2(s01, s23);
}

// transpose LN(V): [b][s][d] -> [b][d][s], 64x64 tiles, conflict-free smem
__global__ void __launch_bounds__(256) vt_kernel()
{
    __shared__ h16 tb[64][66], ts[64][66];
    const int s0 = blockIdx.x * 64;
    const int d0 = blockIdx.y * 64;
    const int b  = blockIdx.z;
    const int t  = threadIdx.x;
    const h16* vb = g_vb + (size_t)b * SEQ * D_MODEL;
    const h16* vs = g_vs + (size_t)b * SEQ * D_MODEL;
#pragma unroll
    for (int q = 0; q < 16; q++) {
        int idx = t + 256 * q;
        int sl = idx >> 6, dl = idx & 63;
        tb[sl][dl] = vb[(size_t)(s0 + sl) * D_MODEL + d0 + dl];
        ts[sl][dl] = vs[(size_t)(s0 + sl) * D_MODEL + d0 + dl];
    }
    __syncthreads();
    h16* ob = g_vtb + (size_t)b * D_MODEL * SEQ;
    h16* os = g_vts + (size_t)b * D_MODEL * SEQ;
#pragma unroll
    for (int q = 0; q < 16; q++) {
        int idx = t + 256 * q;
        int dl = idx >> 6, sl = idx & 63;
        ob[(size_t)(d0 + dl) * SEQ + s0 + sl] = tb[sl][dl];
        os[(size_t)(d0 + dl) * SEQ + s0 + sl] = ts[sl][dl];
    }
}

__global__ void __launch_bounds__(256, 2) qk_kernel()
{
    const size_t bz = blockIdx.z;
    gemm_h3<3>(g_qb + bz * SEQ * D_MODEL, g_qs + bz * SEQ * D_MODEL, D_MODEL,
               g_kb + bz * SEQ * D_MODEL, g_ks + bz * SEQ * D_MODEL, D_MODEL,
               g_S + bz * SEQ * SEQ, SEQ,
               D_MODEL, nullptr);
}

__global__ void __launch_bounds__(256) softmax_kernel()
{
    __shared__ float red[8];
    const size_t row = (size_t)blockIdx.y * SEQ + blockIdx.x;
    const float* p = g_S + row * SEQ;
    const int t = threadIdx.x;

    float4 u0 = reinterpret_cast<const float4*>(p)[t];
    float4 u1 = reinterpret_cast<const float4*>(p)[t + 256];
    float m = fmaxf(fmaxf(fmaxf(u0.x, u0.y), fmaxf(u0.z, u0.w)),
                    fmaxf(fmaxf(u1.x, u1.y), fmaxf(u1.z, u1.w)));
    m = block_reduce_max(m, red);

    u0.x = expf(u0.x - m); u0.y = expf(u0.y - m); u0.z = expf(u0.z - m); u0.w = expf(u0.w - m);
    u1.x = expf(u1.x - m); u1.y = expf(u1.y - m); u1.z = expf(u1.z - m); u1.w = expf(u1.w - m);
    float s = (u0.x + u0.y + u0.z + u0.w) + (u1.x + u1.y + u1.z + u1.w);
    s = block_reduce_sum(s, red);
    const float inv = 1.0f / s;

    u0.x *= inv; u0.y *= inv; u0.z *= inv; u0.w *= inv;
    u1.x *= inv; u1.y *= inv; u1.z *= inv; u1.w *= inv;

    uint32_t b01, s01, b23, s23;
    h16* pb = g_pb + row * SEQ;
    h16* ps = g_ps + row * SEQ;
    h16_split_pack(u0.x, u0.y, b01, s01);
    h16_split_pack(u0.z, u0.w, b23, s23);
    reinterpret_cast<uint2*>(pb)[t]       = make_uint2(b01, b23);
    reinterpret_cast<uint2*>(ps)[t]       = make_uint2(s01, s23);
    h16_split_pack(u1.x, u1.y, b01, s01);
    h16_split_pack(u1.z, u1.w, b23, s23);
    reinterpret_cast<uint2*>(pb)[t + 256] = make_uint2(b01, b23);
    reinterpret_cast<uint2*>(ps)[t + 256] = make_uint2(s01, s23);
}

// O = P @ V: 2-term split (Pb*Vb + Ps*Vb); dropped Pb*Vs contributes ~2.4e-4 rel.
__global__ void __launch_bounds__(256, 2) pv_kernel(float* __restrict__ out)
{
    const size_t bz = blockIdx.z;
    gemm_h3<2>(g_pb  + bz * SEQ * SEQ, g_ps  + bz * SEQ * SEQ, SEQ,
               g_vtb + bz * D_MODEL * SEQ, g_vts + bz * D_MODEL * SEQ, SEQ,
               out   + bz * SEQ * D_MODEL, D_MODEL,
               SEQ, nullptr);
}

// ---------------- launch ----------------
extern "C" void kernel_launch(void* const* d_in, const int* in_sizes, int n_in,
                              void* d_out, int out_size)
{
    const float* x     = (const float*)d_in[0];
    const float* Wq    = (const float*)d_in[1];
    const float* bq    = (const float*)d_in[2];
    const float* Wk    = (const float*)d_in[3];
    const float* bk    = (const float*)d_in[4];
    const float* Wv    = (const float*)d_in[5];
    const float* bv    = (const float*)d_in[6];
    const float* gamma = (const float*)d_in[7];
    const float* beta  = (const float*)d_in[8];
    float* out = (float*)d_out;

    dim3 tpb(256);
    set_bias_kernel<<<1, 32>>>(bq, bk, bv);
    split_all_kernel<<<dim3(MROWS * D_MODEL / 4 / 256, 4), tpb>>>(x, Wq, Wk, Wv);

    proj_kernel   <<<dim3(MROWS / 128, D_MODEL / 128, 3), tpb>>>();
    ln_kernel     <<<dim3(MROWS, 3), tpb>>>(gamma, beta);
    vt_kernel     <<<dim3(SEQ / 64, D_MODEL / 64, BATCH), tpb>>>();
    qk_kernel     <<<dim3(SEQ / 128, SEQ / 128, BATCH), tpb>>>();
    softmax_kernel<<<dim3(SEQ, BATCH), tpb>>>();
    pv_kernel     <<<dim3(SEQ / 128, D_MODEL / 128, BATCH), tpb>>>(out);
}